// round 1
// baseline (speedup 1.0000x reference)
#include <cuda_runtime.h>

// SmoothRankAP (quick_forward, sigmoid rank approx, tau=0.01), B=512.
// out = 1 - mean_q [ (1/npos_q) * sum_{i: t[q,i]=1} sim_pos(q,i)/sim_all(q,i) ]
//
// sim_all(q,i) = sum_j sigmoid((s[q,j]-s[q,i])/tau) + 0.5          (mask removes j==i term of 0.5, then +1)
// sim_pos(q,i) = sum_j sigmoid((s[q,j]-s[q,i])/tau)*t[q,j] - sigmoid((s[q,q]-s[q,i])/tau) + 1
//
// Only positive (q,i) pairs (t[q,i]==1) contribute: ~16 per row -> 32x less
// work than the reference's dense [B,B,B] tensor.

static constexpr int BB = 512;

__device__ float g_ap[BB];  // per-query AP scratch (no allocation allowed)

__global__ __launch_bounds__(256) void smoothap_row_kernel(
    const float* __restrict__ scores,
    const float* __restrict__ target)
{
    __shared__ float ls[BB];      // scores[q,:] * (100 * log2(e)), ready for exp2f
    __shared__ float t[BB];       // target[q,:]
    __shared__ int   poslist[BB];
    __shared__ int   npos_s;
    __shared__ float warp_acc[8];

    const int q   = blockIdx.x;
    const int tid = threadIdx.x;
    const float K = 100.0f * 1.4426950408889634f;  // (1/tau) * log2(e)

    for (int j = tid; j < BB; j += 256) {
        ls[j] = scores[q * BB + j] * K;
        t[j]  = target[q * BB + j];
    }
    __syncthreads();

    // Deterministic positive-list build (cheap: 512 smem reads, serial).
    if (tid == 0) {
        int n = 0;
        for (int j = 0; j < BB; ++j)
            if (t[j] > 0.5f) poslist[n++] = j;
        npos_s = n;
    }
    __syncthreads();

    const int npos = npos_s;   // >= 1 (diagonal always positive)
    const int wid  = tid >> 5;
    const int lane = tid & 31;

    float acc = 0.0f;  // meaningful on lane 0 only

    for (int pi = wid; pi < npos; pi += 8) {
        const int   i   = poslist[pi];
        const float lsi = ls[i];

        // sigmoid((s_j - s_i)/tau) = 1 / (1 + exp2(lsi - ls[j]))
        float sum_all = 0.0f;
        float sum_pos = 0.0f;
        #pragma unroll 4
        for (int j = lane; j < BB; j += 32) {
            const float e   = exp2f(lsi - ls[j]);          // MUFU.EX2; inf/0 saturate correctly
            const float sig = __fdividef(1.0f, 1.0f + e);  // MUFU.RCP; 1/inf -> 0
            sum_all += sig;
            sum_pos += sig * t[j];
        }
        #pragma unroll
        for (int o = 16; o; o >>= 1) {
            sum_all += __shfl_xor_sync(0xffffffffu, sum_all, o);
            sum_pos += __shfl_xor_sync(0xffffffffu, sum_pos, o);
        }
        if (lane == 0) {
            const float sgq = __fdividef(1.0f, 1.0f + exp2f(lsi - ls[q]));
            const float all = sum_all + 0.5f;        // -0.5 (drop j==i) + 1
            const float pos = sum_pos - sgq + 1.0f;  // drop eye(q,j) term, + target[q,i](=1)
            acc += __fdividef(pos, all);
        }
    }

    if (lane == 0) warp_acc[wid] = acc;
    __syncthreads();

    if (tid == 0) {
        float tot = 0.0f;
        #pragma unroll
        for (int w = 0; w < 8; ++w) tot += warp_acc[w];
        g_ap[q] = tot / (float)npos;   // npos == jnp.sum(target, axis=1) exactly
    }
}

__global__ __launch_bounds__(256) void smoothap_reduce_kernel(float* __restrict__ out)
{
    __shared__ float sm[256];
    const int tid = threadIdx.x;
    sm[tid] = g_ap[tid] + g_ap[tid + 256];
    __syncthreads();
    #pragma unroll
    for (int w = 128; w > 0; w >>= 1) {
        if (tid < w) sm[tid] += sm[tid + w];
        __syncthreads();
    }
    if (tid == 0) out[0] = 1.0f - sm[0] * (1.0f / 512.0f);
}

extern "C" void kernel_launch(void* const* d_in, const int* in_sizes, int n_in,
                              void* d_out, int out_size)
{
    const float* scores = (const float*)d_in[0];
    const float* target = (const float*)d_in[1];
    float* out = (float*)d_out;

    smoothap_row_kernel<<<BB, 256>>>(scores, target);
    smoothap_reduce_kernel<<<1, 256>>>(out);
}

// round 2
// speedup vs baseline: 2.1458x; 2.1458x over previous
#include <cuda_runtime.h>

// SmoothRankAP (quick_forward, sigmoid rank approx, tau=0.01), B=512. Fused single kernel.
//
// sigma(x) = 0.5*tanh(x/2) + 0.5, with h[j] = scores[q,j] * 50  (x/2 = (s_j - s_i)/(2*tau))
// T_all = sum_j tanh(h_j - h_i)            -> sim_all = 0.5*T_all + (B/2 + 0.5)
// T_pos = sum_j tanh(h_j - h_i) * t[q,j]   -> sim_pos = 0.5*(T_pos - tanh(h_q - h_i) + npos) + 0.5
// ap[q] = (1/npos) * sum_{i: t=1} sim_pos/sim_all;  out = 1 - mean_q ap[q]

static constexpr int BB = 512;

__device__ float        g_ap[BB];
__device__ unsigned int g_ticket = 0;   // reset by last block each launch -> deterministic replays

__device__ __forceinline__ float tanh_approx(float x) {
    float y;
    asm("tanh.approx.f32 %0, %1;" : "=f"(y) : "f"(x));
    return y;
}

__global__ __launch_bounds__(256) void smoothap_fused_kernel(
    const float* __restrict__ scores,
    const float* __restrict__ target,
    float* __restrict__ out)
{
    __shared__ float h[BB];        // scores[q,:] * 50
    __shared__ float t[BB];        // target[q,:]
    __shared__ int   poslist[BB];
    __shared__ int   c_cnt[16];
    __shared__ int   c_off[16];
    __shared__ int   npos_s;
    __shared__ float warp_acc[8];
    __shared__ int   is_last_s;

    const int q    = blockIdx.x;
    const int tid  = threadIdx.x;
    const int wid  = tid >> 5;
    const int lane = tid & 31;

    // ---- vectorized row staging: 128 threads load scores, 128 load target ----
    if (tid < 128) {
        float4 v = reinterpret_cast<const float4*>(scores + q * BB)[tid];
        h[4 * tid + 0] = v.x * 50.0f;
        h[4 * tid + 1] = v.y * 50.0f;
        h[4 * tid + 2] = v.z * 50.0f;
        h[4 * tid + 3] = v.w * 50.0f;
    } else {
        int k = tid - 128;
        float4 v = reinterpret_cast<const float4*>(target + q * BB)[k];
        t[4 * k + 0] = v.x;
        t[4 * k + 1] = v.y;
        t[4 * k + 2] = v.z;
        t[4 * k + 3] = v.w;
    }
    __syncthreads();

    // ---- parallel order-preserving compaction of positives ----
    // 16 chunks of 32; warp w owns chunks 2w, 2w+1.
    #pragma unroll
    for (int k = 0; k < 2; ++k) {
        int c = 2 * wid + k;
        unsigned m = __ballot_sync(0xffffffffu, t[c * 32 + lane] > 0.5f);
        if (lane == 0) c_cnt[c] = __popc(m);
    }
    __syncthreads();
    if (tid == 0) {                 // 16-element exclusive scan, trivial
        int run = 0;
        #pragma unroll
        for (int c = 0; c < 16; ++c) { c_off[c] = run; run += c_cnt[c]; }
        npos_s = run;
    }
    __syncthreads();
    #pragma unroll
    for (int k = 0; k < 2; ++k) {
        int c = 2 * wid + k;
        int j = c * 32 + lane;
        bool p = t[j] > 0.5f;
        unsigned m = __ballot_sync(0xffffffffu, p);
        if (p) poslist[c_off[c] + __popc(m & ((1u << lane) - 1u))] = j;
    }
    __syncthreads();

    const int   npos  = npos_s;           // >= 1 (diagonal)
    const float hq    = h[q];
    float acc = 0.0f;                     // lane 0 of each warp

    for (int pi = wid; pi < npos; pi += 8) {
        const int   i  = poslist[pi];
        const float hi = h[i];

        float t_all = 0.0f, t_pos = 0.0f;
        #pragma unroll
        for (int k = 0; k < BB / 32; ++k) {
            const int   j  = k * 32 + lane;
            const float th = tanh_approx(h[j] - hi);
            t_all += th;
            t_pos  = fmaf(th, t[j], t_pos);
        }
        #pragma unroll
        for (int o = 16; o; o >>= 1) {
            t_all += __shfl_xor_sync(0xffffffffu, t_all, o);
            t_pos += __shfl_xor_sync(0xffffffffu, t_pos, o);
        }
        if (lane == 0) {
            const float thq     = tanh_approx(hq - hi);
            const float sim_all = 0.5f * t_all + ((float)BB * 0.5f + 0.5f);
            const float sim_pos = 0.5f * (t_pos - thq + (float)npos) + 0.5f;
            acc += __fdividef(sim_pos, sim_all);
        }
    }

    if (lane == 0) warp_acc[wid] = acc;
    __syncthreads();

    if (tid == 0) {
        float tot = 0.0f;
        #pragma unroll
        for (int w = 0; w < 8; ++w) tot += warp_acc[w];
        g_ap[q] = __fdividef(tot, (float)npos);

        __threadfence();                                   // publish g_ap[q]
        unsigned tk = atomicAdd(&g_ticket, 1u);
        is_last_s = (tk == (unsigned)(gridDim.x - 1));
    }
    __syncthreads();

    // ---- last block: deterministic final reduction ----
    if (is_last_s) {
        __shared__ float sm[256];
        float v = __ldcg(&g_ap[tid]) + __ldcg(&g_ap[tid + 256]);
        sm[tid] = v;
        __syncthreads();
        #pragma unroll
        for (int w = 128; w > 0; w >>= 1) {
            if (tid < w) sm[tid] += sm[tid + w];
            __syncthreads();
        }
        if (tid == 0) {
            out[0] = 1.0f - sm[0] * (1.0f / (float)BB);
            g_ticket = 0;                                  // reset for next replay
        }
    }
}

extern "C" void kernel_launch(void* const* d_in, const int* in_sizes, int n_in,
                              void* d_out, int out_size)
{
    const float* scores = (const float*)d_in[0];
    const float* target = (const float*)d_in[1];
    smoothap_fused_kernel<<<BB, 256>>>(scores, target, (float*)d_out);
}